// round 11
// baseline (speedup 1.0000x reference)
#include <cuda_runtime.h>
#include <cuda_bf16.h>

// ---------------- constants ----------------
#define GG 200
#define G2 40000
#define NPTS 128
#define NSAMP 2048
#define STEP_F 0.9765625f        // 2000.0 / 2048, exact
#define CELLS 20                 // cells per block in main kernel (grid 10 x 200)
#define NBND 32                  // threshold slots (cap 30 real)
#define MAXWORK (NPTS * 30)

typedef unsigned long long u64;

__device__ __forceinline__ float kMinLon() { return 95.987f; }
__device__ __forceinline__ float kMinLat() { return 31.3039f; }
__device__ __forceinline__ float kDLon() { return (float)((109.4132 - 95.987) / 200.0); }
__device__ __forceinline__ float kDLat() { return (float)((42.879 - 31.3039) / 200.0); }
__device__ __forceinline__ float kRad()  { return (float)(3.14159265358979323846 / 180.0); }

// ---------------- packed f32x2 helpers ----------------
__device__ __forceinline__ u64 pk(float lo, float hi) {
    u64 r; asm("mov.b64 %0,{%1,%2};" : "=l"(r) : "f"(lo), "f"(hi)); return r;
}
__device__ __forceinline__ void upk(float& lo, float& hi, u64 v) {
    asm("mov.b64 {%0,%1},%2;" : "=f"(lo), "=f"(hi) : "l"(v));
}
__device__ __forceinline__ u64 fma2(u64 a, u64 b, u64 c) {
    u64 r; asm("fma.rn.f32x2 %0,%1,%2,%3;" : "=l"(r) : "l"(a), "l"(b), "l"(c)); return r;
}
__device__ __forceinline__ u64 mul2(u64 a, u64 b) {
    u64 r; asm("mul.rn.f32x2 %0,%1,%2;" : "=l"(r) : "l"(a), "l"(b)); return r;
}
__device__ __forceinline__ u64 K2(float v) {
    unsigned u = __float_as_uint(v); return ((u64)u << 32) | (u64)u;
}

// ---------------- scratch (device globals) ----------------
__device__ __align__(16) float dP[GG * NPTS];
__device__ __align__(16) float dQ[GG * NPTS];
__device__ __align__(16) float dC1[32 * NPTS];   // [j][n]
__device__ __align__(16) float dW2[1024];        // BN-folded w2 [j][k]
__device__ __align__(16) u64 dA1p[16];
__device__ __align__(16) u64 dB2p[16];
__device__ __align__(16) u64 dW3ab[64];
__device__ float dW3e[32];
__device__ float dB3[8];
__device__ float dSlat1[GG], dClat1[GG];
__device__ float dSlat2[NPTS], dTim[NPTS], dPtype[NPTS];
__device__ unsigned dBest;
__device__ unsigned char dSampCls[NPTS * NSAMP];
__device__ __align__(16) float dBnd[NBND * NPTS];   // i-major: [i][n]
__device__ u64 dCls0[NPTS], dCls1[NPTS];            // nibble-packed interval classes
__device__ unsigned dWork[MAXWORK];                 // packed compacted work items
__device__ float dWLo[MAXWORK], dWHi[MAXWORK];      // initial bracket per item
__device__ int dNWork;

// ---------------- packed XLA-matching tanh ----------------
__device__ __forceinline__ void tanh2(u64 z, float* o0, float* o1) {
    float x0, x1; upk(x0, x1, z);
    float cl0 = fminf(fmaxf(x0, -7.90531110763549805f), 7.90531110763549805f);
    float cl1 = fminf(fmaxf(x1, -7.90531110763549805f), 7.90531110763549805f);
    u64 xc = pk(cl0, cl1);
    u64 x2 = mul2(xc, xc);
    u64 np = fma2(x2, K2(-2.76076847742355e-16f), K2(2.00018790482477e-13f));
    np = fma2(np, x2, K2(-8.60467152213735e-11f));
    np = fma2(np, x2, K2(5.12229709037114e-08f));
    np = fma2(np, x2, K2(1.48572235717979e-05f));
    np = fma2(np, x2, K2(6.37261928875436e-04f));
    np = fma2(np, x2, K2(4.89352455891786e-03f));
    np = mul2(np, xc);
    u64 dp = fma2(x2, K2(1.19825839466702e-06f), K2(1.18534705686654e-04f));
    dp = fma2(dp, x2, K2(2.26843463243900e-03f));
    dp = fma2(dp, x2, K2(4.89352518554385e-03f));
    float n0, n1, d0, d1;
    upk(n0, n1, np); upk(d0, d1, dp);
    float r0 = __fdividef(n0, d0);
    float r1 = __fdividef(n1, d1);
    *o0 = (fabsf(x0) < 0.0004f) ? x0 : r0;
    *o1 = (fabsf(x1) < 0.0004f) ? x1 : r1;
}

// ---------------- packed MLP classifier: gd -> class (validated fp sequence) ----------------
__device__ __forceinline__ int eval_cls(float gd,
                                        const u64* __restrict__ c1p,
                                        const float* __restrict__ sW2,
                                        const u64* __restrict__ sA1p,
                                        const u64* __restrict__ sB2p,
                                        const u64* __restrict__ sW3ab,
                                        const float* __restrict__ sW3e,
                                        const float* __restrict__ sB3) {
    u64 gdp = pk(gd, gd);
    u64 acc[16];
#pragma unroll
    for (int t = 0; t < 16; t++) acc[t] = sB2p[t];
#pragma unroll
    for (int j2 = 0; j2 < 16; j2++) {
        u64 z = fma2(sA1p[j2], gdp, c1p[j2]);
        float h0, h1;
        tanh2(z, &h0, &h1);
        {
            u64 hp = pk(h0, h0);
            const ulonglong2* wr = (const ulonglong2*)(sW2 + (2 * j2) * 32);
#pragma unroll
            for (int qq = 0; qq < 8; qq++) {
                ulonglong2 wv = wr[qq];
                acc[qq * 2 + 0] = fma2(hp, wv.x, acc[qq * 2 + 0]);
                acc[qq * 2 + 1] = fma2(hp, wv.y, acc[qq * 2 + 1]);
            }
        }
        {
            u64 hp = pk(h1, h1);
            const ulonglong2* wr = (const ulonglong2*)(sW2 + (2 * j2 + 1) * 32);
#pragma unroll
            for (int qq = 0; qq < 8; qq++) {
                ulonglong2 wv = wr[qq];
                acc[qq * 2 + 0] = fma2(hp, wv.x, acc[qq * 2 + 0]);
                acc[qq * 2 + 1] = fma2(hp, wv.y, acc[qq * 2 + 1]);
            }
        }
    }
    u64 lg01 = pk(sB3[0], sB3[1]);
    u64 lg23 = pk(sB3[2], sB3[3]);
    float lg4 = sB3[4];
    const ulonglong2* w3v = (const ulonglong2*)sW3ab;
#pragma unroll
    for (int k2 = 0; k2 < 16; k2++) {
        float t0, t1;
        tanh2(acc[k2], &t0, &t1);
        {
            ulonglong2 wv = w3v[2 * k2];
            u64 tp = pk(t0, t0);
            lg01 = fma2(tp, wv.x, lg01);
            lg23 = fma2(tp, wv.y, lg23);
            lg4 = __fmaf_rn(t0, sW3e[2 * k2], lg4);
        }
        {
            ulonglong2 wv = w3v[2 * k2 + 1];
            u64 tp = pk(t1, t1);
            lg01 = fma2(tp, wv.x, lg01);
            lg23 = fma2(tp, wv.y, lg23);
            lg4 = __fmaf_rn(t1, sW3e[2 * k2 + 1], lg4);
        }
    }
    float l0, l1, l2, l3;
    upk(l0, l1, lg01);
    upk(l2, l3, lg23);
    int arg = 0;
    float bst = l0;
    if (l1 > bst) { bst = l1; arg = 1; }
    if (l2 > bst) { bst = l2; arg = 2; }
    if (l3 > bst) { bst = l3; arg = 3; }
    if (lg4 > bst) { bst = lg4; arg = 4; }
    return arg;
}

#define LOAD_WEIGHTS()                                                     \
    for (int t = tid; t < 1024; t += blockDim.x) sW2[t] = dW2[t];          \
    if (tid < 16) { sA1p[tid] = dA1p[tid]; sB2p[tid] = dB2p[tid]; }        \
    if (tid < 64) sW3ab[tid] = dW3ab[tid];                                 \
    if (tid < 32) sW3e[tid] = dW3e[tid];                                   \
    if (tid < 5)  sB3[tid] = dB3[tid];

#define LOAD_C1P(n)                                                        \
    u64 c1p[16];                                                           \
    _Pragma("unroll")                                                      \
    for (int j2 = 0; j2 < 16; j2++)                                        \
        c1p[j2] = pk(dC1[(2 * j2) * NPTS + (n)], dC1[(2 * j2 + 1) * NPTS + (n)]);

#define DECL_SMEM_WEIGHTS                                                  \
    __shared__ __align__(16) float sW2[1024];                              \
    __shared__ __align__(16) u64 sW3ab[64];                                \
    __shared__ __align__(16) u64 sA1p[16], sB2p[16];                       \
    __shared__ float sW3e[32];                                             \
    __shared__ float sB3[5];

// ---------------- prep ----------------
__global__ void prep_kernel(const float* __restrict__ x,
                            const float* __restrict__ w1, const float* __restrict__ b1,
                            const float* __restrict__ g1, const float* __restrict__ be1,
                            const float* __restrict__ m1, const float* __restrict__ v1,
                            const float* __restrict__ w2, const float* __restrict__ b2,
                            const float* __restrict__ g2, const float* __restrict__ be2,
                            const float* __restrict__ m2, const float* __restrict__ v2,
                            const float* __restrict__ w3, const float* __restrict__ b3) {
    int tid = threadIdx.x;
    int jb = blockIdx.x;
    __shared__ float sT1[32], sBc1[32], tA1[32], tB2[32];

    if (tid < NPTS) {
        float lon2 = x[tid * 4 + 0];
        float lat2 = x[tid * 4 + 1];
        float latr = __fmul_rn(lat2, kRad());
        float lonr = __fmul_rn(lon2, kRad());
        float sl2, cl2;
        sincosf(latr, &sl2, &cl2);
        float lon1 = __fadd_rn(kMinLon(), __fmul_rn(kDLon(), (float)jb));
        float dl = __fsub_rn(lonr, __fmul_rn(lon1, kRad()));
        float sdl, cdl;
        sincosf(dl, &sdl, &cdl);
        dP[jb * NPTS + tid] = __fmul_rn(cl2, sdl);
        dQ[jb * NPTS + tid] = __fmul_rn(cl2, cdl);
        if (jb == 0) {
            dSlat2[tid] = sl2;
            dTim[tid]   = x[tid * 4 + 2];
            dPtype[tid] = x[tid * 4 + 3];
        }
    }
    if (jb == 0) {
        if (tid < GG) {
            float lat1 = __fadd_rn(kMinLat(), __fmul_rn(kDLat(), (float)tid));
            float s, c;
            sincosf(__fmul_rn(lat1, kRad()), &s, &c);
            dSlat1[tid] = s;
            dClat1[tid] = c;
        }
        if (tid < 32) {
            float s1 = g1[tid] / sqrtf(v1[tid] + 1e-5f);
            tA1[tid]  = w1[tid] * s1 * 0.01f;
            sT1[tid]  = w1[32 + tid] * s1 * 0.01f;
            sBc1[tid] = (b1[tid] - m1[tid]) * s1 + be1[tid];
            float s2 = g2[tid] / sqrtf(v2[tid] + 1e-5f);
            tB2[tid] = (b2[tid] - m2[tid]) * s2 + be2[tid];
            for (int j = 0; j < 32; j++)
                dW2[j * 32 + tid] = w2[j * 32 + tid] * s2;
            dW3ab[tid * 2 + 0] = pk(w3[tid * 5 + 0], w3[tid * 5 + 1]);
            dW3ab[tid * 2 + 1] = pk(w3[tid * 5 + 2], w3[tid * 5 + 3]);
            dW3e[tid] = w3[tid * 5 + 4];
        }
        if (tid < 5)   dB3[tid] = b3[tid];
        if (tid == 0)  { dBest = 0u; dNWork = 0; }
        __syncthreads();
        if (tid < 16) {
            dA1p[tid] = pk(tA1[2 * tid], tA1[2 * tid + 1]);
            dB2p[tid] = pk(tB2[2 * tid], tB2[2 * tid + 1]);
        }
        for (int idx = tid; idx < 32 * NPTS; idx += blockDim.x) {
            int j = idx >> 7, n = idx & 127;
            dC1[idx] = __fmaf_rn(sT1[j], x[n * 4 + 2], sBc1[j]);
        }
    }
}

// ---------------- K2: sample class(gd), 1 eval per thread ----------------
__global__ __launch_bounds__(128) void sample_kernel() {
    DECL_SMEM_WEIGHTS
    int tid = threadIdx.x;
    int n = blockIdx.x;

    LOAD_WEIGHTS();
    LOAD_C1P(n);
    __syncthreads();

    int s = blockIdx.y * 128 + tid;
    int c = eval_cls(__fmul_rn((float)s, STEP_F), c1p, sW2, sA1p, sB2p, sW3ab, sW3e, sB3);
    dSampCls[n * NSAMP + s] = (unsigned char)c;
}

// ---------------- K3: scan — transitions, class table, compacted work list ----------------
__global__ __launch_bounds__(128) void scan_kernel() {
    __shared__ int sList[96];
    __shared__ int sCnt;
    int tid = threadIdx.x;
    int n = blockIdx.x;
    if (tid == 0) sCnt = 0;
    __syncthreads();

    const unsigned char* sc = dSampCls + n * NSAMP;
    int sbeg = tid * 16;
    for (int s = sbeg; s < sbeg + 16 && s < NSAMP - 1; s++) {
        if (sc[s] != sc[s + 1]) {
            int p = atomicAdd(&sCnt, 1);
            if (p < 96) sList[p] = s;
        }
    }
    __syncthreads();

    if (tid == 0) {
        int m = sCnt; if (m > 96) m = 96;
        for (int a = 1; a < m; a++) {
            int key = sList[a]; int b = a - 1;
            while (b >= 0 && sList[b] > key) { sList[b + 1] = sList[b]; b--; }
            sList[b + 1] = key;
        }
        int nb = (m > 30) ? 30 : m;
        // interval class table
        u64 c0 = 0, c1v = 0;
        int cur = sc[0];
        for (int j = 0; j < 32; j++) {
            if (j >= 1 && j - 1 < nb) cur = sc[sList[j - 1] + 1];
            if (j < 16) c0 |= (u64)cur << (4 * j);
            else        c1v |= (u64)cur << (4 * (j - 16));
        }
        dCls0[n] = c0;
        dCls1[n] = c1v;
        // append compacted work items: n[0:7) cl[18:21) ch[21:24) b[24:29)
        int base = atomicAdd(&dNWork, nb);
        for (int j = 0; j < nb; j++) {
            int s = sList[j];
            unsigned item = (unsigned)n
                          | ((unsigned)sc[s] << 18) | ((unsigned)sc[s + 1] << 21)
                          | ((unsigned)j << 24);
            dWork[base + j] = item;
            dWLo[base + j] = __fmul_rn((float)s, STEP_F);
            dWHi[base + j] = __fmul_rn((float)(s + 1), STEP_F);
        }
    }
    __syncthreads();
    const float INF = __int_as_float(0x7f800000);
    if (tid < NBND) dBnd[tid * NPTS + n] = INF;   // refine overwrites real ones
}

// ---------------- K4: refine — block of 256 per item, iterative 257-ary to exact float ----------------
__global__ __launch_bounds__(256) void refine_kernel() {
    DECL_SMEM_WEIGHTS
    __shared__ float sMid[256];
    __shared__ unsigned sBal[8];
    __shared__ float sLo, sHi;
    __shared__ int sDone;
    int tid = threadIdx.x;
    int i = blockIdx.x;
    if (i >= dNWork) return;

    unsigned wv = dWork[i];
    int n  = (int)(wv & 127u);
    int cl = (int)((wv >> 18) & 7u);
    int b  = (int)((wv >> 24) & 31u);

    LOAD_WEIGHTS();
    LOAD_C1P(n);
    if (tid == 0) { sLo = dWLo[i]; sHi = dWHi[i]; sDone = 0; }
    __syncthreads();

    for (int lev = 0; lev < 12; lev++) {
        float lo = sLo, hi = sHi;
        float wdt = __fsub_rn(hi, lo);
        float mid = __fmaf_rn(wdt, __fmul_rn((float)(tid + 1), (1.0f / 257.0f)), lo);
        mid = fminf(fmaxf(mid, lo), hi);
        int cm;
        if (mid > lo && mid < hi)
            cm = eval_cls(mid, c1p, sW2, sA1p, sB2p, sW3ab, sW3e, sB3);
        else
            cm = (mid <= lo) ? cl : (cl + 1) % 8;   // degenerate-at-hi votes "differs"
        sMid[tid] = mid;
        unsigned bal = __ballot_sync(0xffffffffu, cm != cl);
        if ((tid & 31) == 0) sBal[tid >> 5] = bal;
        __syncthreads();
        if (tid == 0) {
            int f = 256;
            for (int w = 0; w < 8; w++) {
                if (sBal[w]) { f = w * 32 + __ffs(sBal[w]) - 1; break; }
            }
            float nlo, nhi;
            if (f == 256) { nlo = sMid[255]; nhi = hi; }
            else { nhi = sMid[f]; nlo = (f == 0) ? lo : sMid[f - 1]; }
            nlo = fmaxf(nlo, lo);
            nhi = fminf(nhi, hi);
            sLo = nlo; sHi = nhi;
            float m = __fmul_rn(__fadd_rn(nlo, nhi), 0.5f);
            if (!(m > nlo && m < nhi)) sDone = 1;   // adjacent floats: threshold = nhi
        }
        __syncthreads();
        if (sDone) break;
    }
    if (tid == 0) dBnd[b * NPTS + n] = sHi;
}

// ---------------- K5: main — 2D grid (10 x 200), no integer division ----------------
__global__ __launch_bounds__(128) void main_kernel() {
    __shared__ __align__(16) float sB[NBND * NPTS];  // 16KB, [i][n]
    __shared__ unsigned sCnt[CELLS][4];
    int tid = threadIdx.x;

    for (int t = tid; t < NBND * NPTS; t += 128) sB[t] = dBnd[t];
    float slat2 = dSlat2[tid];
    float ptype = dPtype[tid];
    u64 pc0 = dCls0[tid], pc1 = dCls1[tid];

    int i = blockIdx.y;                 // lat row, fixed per block
    int jgbase = blockIdx.x * CELLS;    // lon col base
    float sl1 = dSlat1[i], cl1 = dClat1[i];
    __syncthreads();

#pragma unroll 2
    for (int cc = 0; cc < CELLS; cc++) {
        int jg = jgbase + cc;
        float p = dP[jg * NPTS + tid];
        float q = dQ[jg * NPTS + tid];
        float v = __fsub_rn(__fmul_rn(cl1, slat2), __fmul_rn(sl1, q));
        float w = __fadd_rn(__fmul_rn(sl1, slat2), __fmul_rn(cl1, q));
        float y = sqrtf(__fadd_rn(__fmul_rn(p, p), __fmul_rn(v, v)));
        float gd = __fmul_rn(atan2f(y, w), 6371.0f);

        int idx = 0;
#pragma unroll
        for (int st = 16; st >= 1; st >>= 1) {
            int j = idx + st;
            if (sB[(j - 1) * NPTS + tid] <= gd) idx = j;
        }
        int cls = (int)(((idx < 16) ? (pc0 >> (4 * idx)) : (pc1 >> (4 * (idx - 16)))) & 15u);
        bool match = ((float)cls == ptype);
        unsigned bal = __ballot_sync(0xffffffffu, match);
        if ((tid & 31) == 0) sCnt[cc][tid >> 5] = __popc(bal);
    }
    __syncthreads();
    if (tid == 0) {
        int kbase = i * GG + jgbase;
        unsigned best = 0;
        for (int cc = 0; cc < CELLS; cc++) {
            unsigned num = sCnt[cc][0] + sCnt[cc][1] + sCnt[cc][2] + sCnt[cc][3];
            unsigned key = (num << 16) | (unsigned)(G2 - 1 - (kbase + cc));
            if (key > best) best = key;
        }
        atomicMax(&dBest, best);
    }
}

// ---------------- K6: finalize ----------------
__global__ void finalize_kernel(float* __restrict__ out) {
    int tid = threadIdx.x;
    unsigned val = dBest;
    int k = (G2 - 1) - (int)(val & 0xFFFFu);
    int i = k / GG;
    int jg = k - i * GG;

    float slat2 = dSlat2[tid];
    float sl1 = dSlat1[i], cl1 = dClat1[i];
    float p = dP[jg * NPTS + tid];
    float q = dQ[jg * NPTS + tid];
    float v = __fsub_rn(__fmul_rn(cl1, slat2), __fmul_rn(sl1, q));
    float w = __fadd_rn(__fmul_rn(sl1, slat2), __fmul_rn(cl1, q));
    float y = sqrtf(__fadd_rn(__fmul_rn(p, p), __fmul_rn(v, v)));
    float gd = __fmul_rn(atan2f(y, w), 6371.0f);

    int idx = 0;
#pragma unroll
    for (int st = 16; st >= 1; st >>= 1) {
        int j = idx + st;
        if (dBnd[(j - 1) * NPTS + tid] <= gd) idx = j;
    }
    u64 pc0 = dCls0[tid], pc1 = dCls1[tid];
    int cls = (int)(((idx < 16) ? (pc0 >> (4 * idx)) : (pc1 >> (4 * (idx - 16)))) & 15u);

    out[tid] = (float)cls;
    out[128 + 2 * tid]     = gd;
    out[128 + 2 * tid + 1] = dTim[tid];
    if (tid == 0) {
        out[384] = (float)(val >> 16);
        out[385] = __fadd_rn(kMinLon(), __fmul_rn(kDLon(), (float)jg));
        out[386] = __fadd_rn(kMinLat(), __fmul_rn(kDLat(), (float)i));
    }
}

// ---------------- launch ----------------
extern "C" void kernel_launch(void* const* d_in, const int* in_sizes, int n_in,
                              void* d_out, int out_size) {
    const float* x   = (const float*)d_in[0];
    const float* w1  = (const float*)d_in[1];
    const float* b1  = (const float*)d_in[2];
    const float* g1  = (const float*)d_in[3];
    const float* be1 = (const float*)d_in[4];
    const float* m1  = (const float*)d_in[5];
    const float* v1  = (const float*)d_in[6];
    const float* w2  = (const float*)d_in[7];
    const float* b2  = (const float*)d_in[8];
    const float* g2  = (const float*)d_in[9];
    const float* be2 = (const float*)d_in[10];
    const float* m2  = (const float*)d_in[11];
    const float* v2  = (const float*)d_in[12];
    const float* w3  = (const float*)d_in[13];
    const float* b3  = (const float*)d_in[14];

    prep_kernel<<<GG, 256>>>(x, w1, b1, g1, be1, m1, v1,
                             w2, b2, g2, be2, m2, v2, w3, b3);
    sample_kernel<<<dim3(NPTS, NSAMP / 128), 128>>>();
    scan_kernel<<<NPTS, 128>>>();
    refine_kernel<<<MAXWORK, 256>>>();
    main_kernel<<<dim3(GG / CELLS, GG), 128>>>();
    finalize_kernel<<<1, 128>>>((float*)d_out);
}

// round 12
// speedup vs baseline: 1.6262x; 1.6262x over previous
#include <cuda_runtime.h>
#include <cuda_bf16.h>

// ---------------- constants ----------------
#define GG 200
#define G2 40000
#define NPTS 128
#define NSAMP 2048
#define STEP_F 0.9765625f        // 2000.0 / 2048, exact
#define CELLS 20                 // cells per block in main kernel (grid 10 x 200)
#define NBND 32                  // threshold slots (cap 30 real)
#define MAXWORK (NPTS * 30)

typedef unsigned long long u64;

__device__ __forceinline__ float kMinLon() { return 95.987f; }
__device__ __forceinline__ float kMinLat() { return 31.3039f; }
__device__ __forceinline__ float kDLon() { return (float)((109.4132 - 95.987) / 200.0); }
__device__ __forceinline__ float kDLat() { return (float)((42.879 - 31.3039) / 200.0); }
__device__ __forceinline__ float kRad()  { return (float)(3.14159265358979323846 / 180.0); }

// ---------------- packed f32x2 helpers ----------------
__device__ __forceinline__ u64 pk(float lo, float hi) {
    u64 r; asm("mov.b64 %0,{%1,%2};" : "=l"(r) : "f"(lo), "f"(hi)); return r;
}
__device__ __forceinline__ void upk(float& lo, float& hi, u64 v) {
    asm("mov.b64 {%0,%1},%2;" : "=f"(lo), "=f"(hi) : "l"(v));
}
__device__ __forceinline__ u64 fma2(u64 a, u64 b, u64 c) {
    u64 r; asm("fma.rn.f32x2 %0,%1,%2,%3;" : "=l"(r) : "l"(a), "l"(b), "l"(c)); return r;
}
__device__ __forceinline__ u64 mul2(u64 a, u64 b) {
    u64 r; asm("mul.rn.f32x2 %0,%1,%2;" : "=l"(r) : "l"(a), "l"(b)); return r;
}
__device__ __forceinline__ u64 K2(float v) {
    unsigned u = __float_as_uint(v); return ((u64)u << 32) | (u64)u;
}

// ---------------- scratch (device globals) ----------------
__device__ __align__(16) float dP[GG * NPTS];
__device__ __align__(16) float dQ[GG * NPTS];
__device__ __align__(16) float dC1[32 * NPTS];   // [j][n]
__device__ __align__(16) float dW2[1024];        // BN-folded w2 [j][k]
__device__ __align__(16) u64 dA1p[16];
__device__ __align__(16) u64 dB2p[16];
__device__ __align__(16) u64 dW3ab[64];
__device__ float dW3e[32];
__device__ float dB3[8];
__device__ float dSlat1[GG], dClat1[GG];
__device__ float dSlat2[NPTS], dTim[NPTS], dPtype[NPTS];
__device__ unsigned dBest;
__device__ unsigned char dSampCls[NPTS * NSAMP];
__device__ __align__(16) float dBnd[NBND * NPTS];   // i-major: [i][n]
__device__ u64 dCls0[NPTS], dCls1[NPTS];            // nibble-packed interval classes
__device__ unsigned dWork[MAXWORK];                 // packed compacted work items
__device__ float dWLo[MAXWORK], dWHi[MAXWORK];      // initial bracket per item
__device__ int dNWork;

// ---------------- packed XLA-matching tanh ----------------
__device__ __forceinline__ void tanh2(u64 z, float* o0, float* o1) {
    float x0, x1; upk(x0, x1, z);
    float cl0 = fminf(fmaxf(x0, -7.90531110763549805f), 7.90531110763549805f);
    float cl1 = fminf(fmaxf(x1, -7.90531110763549805f), 7.90531110763549805f);
    u64 xc = pk(cl0, cl1);
    u64 x2 = mul2(xc, xc);
    u64 np = fma2(x2, K2(-2.76076847742355e-16f), K2(2.00018790482477e-13f));
    np = fma2(np, x2, K2(-8.60467152213735e-11f));
    np = fma2(np, x2, K2(5.12229709037114e-08f));
    np = fma2(np, x2, K2(1.48572235717979e-05f));
    np = fma2(np, x2, K2(6.37261928875436e-04f));
    np = fma2(np, x2, K2(4.89352455891786e-03f));
    np = mul2(np, xc);
    u64 dp = fma2(x2, K2(1.19825839466702e-06f), K2(1.18534705686654e-04f));
    dp = fma2(dp, x2, K2(2.26843463243900e-03f));
    dp = fma2(dp, x2, K2(4.89352518554385e-03f));
    float n0, n1, d0, d1;
    upk(n0, n1, np); upk(d0, d1, dp);
    float r0 = __fdividef(n0, d0);
    float r1 = __fdividef(n1, d1);
    *o0 = (fabsf(x0) < 0.0004f) ? x0 : r0;
    *o1 = (fabsf(x1) < 0.0004f) ? x1 : r1;
}

// ---------------- packed MLP classifier: gd -> class (validated fp sequence) ----------------
__device__ __forceinline__ int eval_cls(float gd,
                                        const u64* __restrict__ c1p,
                                        const float* __restrict__ sW2,
                                        const u64* __restrict__ sA1p,
                                        const u64* __restrict__ sB2p,
                                        const u64* __restrict__ sW3ab,
                                        const float* __restrict__ sW3e,
                                        const float* __restrict__ sB3) {
    u64 gdp = pk(gd, gd);
    u64 acc[16];
#pragma unroll
    for (int t = 0; t < 16; t++) acc[t] = sB2p[t];
#pragma unroll
    for (int j2 = 0; j2 < 16; j2++) {
        u64 z = fma2(sA1p[j2], gdp, c1p[j2]);
        float h0, h1;
        tanh2(z, &h0, &h1);
        {
            u64 hp = pk(h0, h0);
            const ulonglong2* wr = (const ulonglong2*)(sW2 + (2 * j2) * 32);
#pragma unroll
            for (int qq = 0; qq < 8; qq++) {
                ulonglong2 wv = wr[qq];
                acc[qq * 2 + 0] = fma2(hp, wv.x, acc[qq * 2 + 0]);
                acc[qq * 2 + 1] = fma2(hp, wv.y, acc[qq * 2 + 1]);
            }
        }
        {
            u64 hp = pk(h1, h1);
            const ulonglong2* wr = (const ulonglong2*)(sW2 + (2 * j2 + 1) * 32);
#pragma unroll
            for (int qq = 0; qq < 8; qq++) {
                ulonglong2 wv = wr[qq];
                acc[qq * 2 + 0] = fma2(hp, wv.x, acc[qq * 2 + 0]);
                acc[qq * 2 + 1] = fma2(hp, wv.y, acc[qq * 2 + 1]);
            }
        }
    }
    u64 lg01 = pk(sB3[0], sB3[1]);
    u64 lg23 = pk(sB3[2], sB3[3]);
    float lg4 = sB3[4];
    const ulonglong2* w3v = (const ulonglong2*)sW3ab;
#pragma unroll
    for (int k2 = 0; k2 < 16; k2++) {
        float t0, t1;
        tanh2(acc[k2], &t0, &t1);
        {
            ulonglong2 wv = w3v[2 * k2];
            u64 tp = pk(t0, t0);
            lg01 = fma2(tp, wv.x, lg01);
            lg23 = fma2(tp, wv.y, lg23);
            lg4 = __fmaf_rn(t0, sW3e[2 * k2], lg4);
        }
        {
            ulonglong2 wv = w3v[2 * k2 + 1];
            u64 tp = pk(t1, t1);
            lg01 = fma2(tp, wv.x, lg01);
            lg23 = fma2(tp, wv.y, lg23);
            lg4 = __fmaf_rn(t1, sW3e[2 * k2 + 1], lg4);
        }
    }
    float l0, l1, l2, l3;
    upk(l0, l1, lg01);
    upk(l2, l3, lg23);
    int arg = 0;
    float bst = l0;
    if (l1 > bst) { bst = l1; arg = 1; }
    if (l2 > bst) { bst = l2; arg = 2; }
    if (l3 > bst) { bst = l3; arg = 3; }
    if (lg4 > bst) { bst = lg4; arg = 4; }
    return arg;
}

#define LOAD_WEIGHTS()                                                     \
    for (int t = tid; t < 1024; t += blockDim.x) sW2[t] = dW2[t];          \
    if (tid < 16) { sA1p[tid] = dA1p[tid]; sB2p[tid] = dB2p[tid]; }        \
    if (tid < 64) sW3ab[tid] = dW3ab[tid];                                 \
    if (tid < 32) sW3e[tid] = dW3e[tid];                                   \
    if (tid < 5)  sB3[tid] = dB3[tid];

#define LOAD_C1P(n)                                                        \
    u64 c1p[16];                                                           \
    _Pragma("unroll")                                                      \
    for (int j2 = 0; j2 < 16; j2++)                                        \
        c1p[j2] = pk(dC1[(2 * j2) * NPTS + (n)], dC1[(2 * j2 + 1) * NPTS + (n)]);

#define DECL_SMEM_WEIGHTS                                                  \
    __shared__ __align__(16) float sW2[1024];                              \
    __shared__ __align__(16) u64 sW3ab[64];                                \
    __shared__ __align__(16) u64 sA1p[16], sB2p[16];                       \
    __shared__ float sW3e[32];                                             \
    __shared__ float sB3[5];

// ---------------- prep ----------------
__global__ void prep_kernel(const float* __restrict__ x,
                            const float* __restrict__ w1, const float* __restrict__ b1,
                            const float* __restrict__ g1, const float* __restrict__ be1,
                            const float* __restrict__ m1, const float* __restrict__ v1,
                            const float* __restrict__ w2, const float* __restrict__ b2,
                            const float* __restrict__ g2, const float* __restrict__ be2,
                            const float* __restrict__ m2, const float* __restrict__ v2,
                            const float* __restrict__ w3, const float* __restrict__ b3) {
    int tid = threadIdx.x;
    int jb = blockIdx.x;
    __shared__ float sT1[32], sBc1[32], tA1[32], tB2[32];

    if (tid < NPTS) {
        float lon2 = x[tid * 4 + 0];
        float lat2 = x[tid * 4 + 1];
        float latr = __fmul_rn(lat2, kRad());
        float lonr = __fmul_rn(lon2, kRad());
        float sl2, cl2;
        sincosf(latr, &sl2, &cl2);
        float lon1 = __fadd_rn(kMinLon(), __fmul_rn(kDLon(), (float)jb));
        float dl = __fsub_rn(lonr, __fmul_rn(lon1, kRad()));
        float sdl, cdl;
        sincosf(dl, &sdl, &cdl);
        dP[jb * NPTS + tid] = __fmul_rn(cl2, sdl);
        dQ[jb * NPTS + tid] = __fmul_rn(cl2, cdl);
        if (jb == 0) {
            dSlat2[tid] = sl2;
            dTim[tid]   = x[tid * 4 + 2];
            dPtype[tid] = x[tid * 4 + 3];
        }
    }
    if (jb == 0) {
        if (tid < GG) {
            float lat1 = __fadd_rn(kMinLat(), __fmul_rn(kDLat(), (float)tid));
            float s, c;
            sincosf(__fmul_rn(lat1, kRad()), &s, &c);
            dSlat1[tid] = s;
            dClat1[tid] = c;
        }
        if (tid < 32) {
            float s1 = g1[tid] / sqrtf(v1[tid] + 1e-5f);
            tA1[tid]  = w1[tid] * s1 * 0.01f;
            sT1[tid]  = w1[32 + tid] * s1 * 0.01f;
            sBc1[tid] = (b1[tid] - m1[tid]) * s1 + be1[tid];
            float s2 = g2[tid] / sqrtf(v2[tid] + 1e-5f);
            tB2[tid] = (b2[tid] - m2[tid]) * s2 + be2[tid];
            for (int j = 0; j < 32; j++)
                dW2[j * 32 + tid] = w2[j * 32 + tid] * s2;
            dW3ab[tid * 2 + 0] = pk(w3[tid * 5 + 0], w3[tid * 5 + 1]);
            dW3ab[tid * 2 + 1] = pk(w3[tid * 5 + 2], w3[tid * 5 + 3]);
            dW3e[tid] = w3[tid * 5 + 4];
        }
        if (tid < 5)   dB3[tid] = b3[tid];
        if (tid == 0)  { dBest = 0u; dNWork = 0; }
        __syncthreads();
        if (tid < 16) {
            dA1p[tid] = pk(tA1[2 * tid], tA1[2 * tid + 1]);
            dB2p[tid] = pk(tB2[2 * tid], tB2[2 * tid + 1]);
        }
        for (int idx = tid; idx < 32 * NPTS; idx += blockDim.x) {
            int j = idx >> 7, n = idx & 127;
            dC1[idx] = __fmaf_rn(sT1[j], x[n * 4 + 2], sBc1[j]);
        }
    }
}

// ---------------- K2: sample class(gd), 1 eval per thread ----------------
__global__ __launch_bounds__(128) void sample_kernel() {
    DECL_SMEM_WEIGHTS
    int tid = threadIdx.x;
    int n = blockIdx.x;

    LOAD_WEIGHTS();
    LOAD_C1P(n);
    __syncthreads();

    int s = blockIdx.y * 128 + tid;
    int c = eval_cls(__fmul_rn((float)s, STEP_F), c1p, sW2, sA1p, sB2p, sW3ab, sW3e, sB3);
    dSampCls[n * NSAMP + s] = (unsigned char)c;
}

// ---------------- K3: scan — transitions, class table, compacted work list ----------------
__global__ __launch_bounds__(128) void scan_kernel() {
    __shared__ int sList[96];
    __shared__ int sCnt;
    int tid = threadIdx.x;
    int n = blockIdx.x;
    if (tid == 0) sCnt = 0;
    __syncthreads();

    const unsigned char* sc = dSampCls + n * NSAMP;
    int sbeg = tid * 16;
    for (int s = sbeg; s < sbeg + 16 && s < NSAMP - 1; s++) {
        if (sc[s] != sc[s + 1]) {
            int p = atomicAdd(&sCnt, 1);
            if (p < 96) sList[p] = s;
        }
    }
    __syncthreads();

    if (tid == 0) {
        int m = sCnt; if (m > 96) m = 96;
        for (int a = 1; a < m; a++) {
            int key = sList[a]; int b = a - 1;
            while (b >= 0 && sList[b] > key) { sList[b + 1] = sList[b]; b--; }
            sList[b + 1] = key;
        }
        int nb = (m > 30) ? 30 : m;
        // interval class table
        u64 c0 = 0, c1v = 0;
        int cur = sc[0];
        for (int j = 0; j < 32; j++) {
            if (j >= 1 && j - 1 < nb) cur = sc[sList[j - 1] + 1];
            if (j < 16) c0 |= (u64)cur << (4 * j);
            else        c1v |= (u64)cur << (4 * (j - 16));
        }
        dCls0[n] = c0;
        dCls1[n] = c1v;
        // append compacted work items: n[0:7) cl[18:21) ch[21:24) b[24:29)
        int base = atomicAdd(&dNWork, nb);
        for (int j = 0; j < nb; j++) {
            int s = sList[j];
            unsigned item = (unsigned)n
                          | ((unsigned)sc[s] << 18) | ((unsigned)sc[s + 1] << 21)
                          | ((unsigned)j << 24);
            dWork[base + j] = item;
            dWLo[base + j] = __fmul_rn((float)s, STEP_F);
            dWHi[base + j] = __fmul_rn((float)(s + 1), STEP_F);
        }
    }
    __syncthreads();
    const float INF = __int_as_float(0x7f800000);
    if (tid < NBND) dBnd[tid * NPTS + n] = INF;   // refine overwrites real ones
}

// ---------------- K4: refine — block of 64 per item, iterative 65-ary to exact float ----------------
__global__ __launch_bounds__(64) void refine_kernel() {
    DECL_SMEM_WEIGHTS
    __shared__ float sMid[64];
    __shared__ unsigned sBal2[2];
    __shared__ float sLo, sHi;
    __shared__ int sDone;
    int tid = threadIdx.x;
    int i = blockIdx.x;
    if (i >= dNWork) return;

    unsigned wv = dWork[i];
    int n  = (int)(wv & 127u);
    int cl = (int)((wv >> 18) & 7u);
    int b  = (int)((wv >> 24) & 31u);

    LOAD_WEIGHTS();
    LOAD_C1P(n);
    if (tid == 0) { sLo = dWLo[i]; sHi = dWHi[i]; sDone = 0; }
    __syncthreads();

    for (int lev = 0; lev < 16; lev++) {
        float lo = sLo, hi = sHi;
        float wdt = __fsub_rn(hi, lo);
        float mid = __fmaf_rn(wdt, __fmul_rn((float)(tid + 1), (1.0f / 65.0f)), lo);
        mid = fminf(fmaxf(mid, lo), hi);
        int cm;
        if (mid > lo && mid < hi)
            cm = eval_cls(mid, c1p, sW2, sA1p, sB2p, sW3ab, sW3e, sB3);
        else
            cm = (mid <= lo) ? cl : (cl + 1) % 8;   // degenerate-at-hi votes "differs"
        sMid[tid] = mid;
        unsigned bal = __ballot_sync(0xffffffffu, cm != cl);
        if ((tid & 31) == 0) sBal2[tid >> 5] = bal;
        __syncthreads();
        if (tid == 0) {
            int f = 64;
            if (sBal2[0]) f = __ffs(sBal2[0]) - 1;
            else if (sBal2[1]) f = 32 + __ffs(sBal2[1]) - 1;
            float nlo, nhi;
            if (f == 64) { nlo = sMid[63]; nhi = hi; }
            else { nhi = sMid[f]; nlo = (f == 0) ? lo : sMid[f - 1]; }
            nlo = fmaxf(nlo, lo);
            nhi = fminf(nhi, hi);
            sLo = nlo; sHi = nhi;
            float m = __fmul_rn(__fadd_rn(nlo, nhi), 0.5f);
            if (!(m > nlo && m < nhi)) sDone = 1;   // adjacent floats: threshold = nhi
        }
        __syncthreads();
        if (sDone) break;
    }
    if (tid == 0) dBnd[b * NPTS + n] = sHi;
}

// ---------------- K5: main — 2D grid (10 x 200), no integer division ----------------
__global__ __launch_bounds__(128) void main_kernel() {
    __shared__ __align__(16) float sB[NBND * NPTS];  // 16KB, [i][n]
    __shared__ unsigned sCnt[CELLS][4];
    int tid = threadIdx.x;

    for (int t = tid; t < NBND * NPTS; t += 128) sB[t] = dBnd[t];
    float slat2 = dSlat2[tid];
    float ptype = dPtype[tid];
    u64 pc0 = dCls0[tid], pc1 = dCls1[tid];

    int i = blockIdx.y;                 // lat row, fixed per block
    int jgbase = blockIdx.x * CELLS;    // lon col base
    float sl1 = dSlat1[i], cl1 = dClat1[i];
    __syncthreads();

#pragma unroll 2
    for (int cc = 0; cc < CELLS; cc++) {
        int jg = jgbase + cc;
        float p = dP[jg * NPTS + tid];
        float q = dQ[jg * NPTS + tid];
        float v = __fsub_rn(__fmul_rn(cl1, slat2), __fmul_rn(sl1, q));
        float w = __fadd_rn(__fmul_rn(sl1, slat2), __fmul_rn(cl1, q));
        float y = sqrtf(__fadd_rn(__fmul_rn(p, p), __fmul_rn(v, v)));
        float gd = __fmul_rn(atan2f(y, w), 6371.0f);

        int idx = 0;
#pragma unroll
        for (int st = 16; st >= 1; st >>= 1) {
            int j = idx + st;
            if (sB[(j - 1) * NPTS + tid] <= gd) idx = j;
        }
        int cls = (int)(((idx < 16) ? (pc0 >> (4 * idx)) : (pc1 >> (4 * (idx - 16)))) & 15u);
        bool match = ((float)cls == ptype);
        unsigned bal = __ballot_sync(0xffffffffu, match);
        if ((tid & 31) == 0) sCnt[cc][tid >> 5] = __popc(bal);
    }
    __syncthreads();
    if (tid == 0) {
        int kbase = i * GG + jgbase;
        unsigned best = 0;
        for (int cc = 0; cc < CELLS; cc++) {
            unsigned num = sCnt[cc][0] + sCnt[cc][1] + sCnt[cc][2] + sCnt[cc][3];
            unsigned key = (num << 16) | (unsigned)(G2 - 1 - (kbase + cc));
            if (key > best) best = key;
        }
        atomicMax(&dBest, best);
    }
}

// ---------------- K6: finalize ----------------
__global__ void finalize_kernel(float* __restrict__ out) {
    int tid = threadIdx.x;
    unsigned val = dBest;
    int k = (G2 - 1) - (int)(val & 0xFFFFu);
    int i = k / GG;
    int jg = k - i * GG;

    float slat2 = dSlat2[tid];
    float sl1 = dSlat1[i], cl1 = dClat1[i];
    float p = dP[jg * NPTS + tid];
    float q = dQ[jg * NPTS + tid];
    float v = __fsub_rn(__fmul_rn(cl1, slat2), __fmul_rn(sl1, q));
    float w = __fadd_rn(__fmul_rn(sl1, slat2), __fmul_rn(cl1, q));
    float y = sqrtf(__fadd_rn(__fmul_rn(p, p), __fmul_rn(v, v)));
    float gd = __fmul_rn(atan2f(y, w), 6371.0f);

    int idx = 0;
#pragma unroll
    for (int st = 16; st >= 1; st >>= 1) {
        int j = idx + st;
        if (dBnd[(j - 1) * NPTS + tid] <= gd) idx = j;
    }
    u64 pc0 = dCls0[tid], pc1 = dCls1[tid];
    int cls = (int)(((idx < 16) ? (pc0 >> (4 * idx)) : (pc1 >> (4 * (idx - 16)))) & 15u);

    out[tid] = (float)cls;
    out[128 + 2 * tid]     = gd;
    out[128 + 2 * tid + 1] = dTim[tid];
    if (tid == 0) {
        out[384] = (float)(val >> 16);
        out[385] = __fadd_rn(kMinLon(), __fmul_rn(kDLon(), (float)jg));
        out[386] = __fadd_rn(kMinLat(), __fmul_rn(kDLat(), (float)i));
    }
}

// ---------------- launch ----------------
extern "C" void kernel_launch(void* const* d_in, const int* in_sizes, int n_in,
                              void* d_out, int out_size) {
    const float* x   = (const float*)d_in[0];
    const float* w1  = (const float*)d_in[1];
    const float* b1  = (const float*)d_in[2];
    const float* g1  = (const float*)d_in[3];
    const float* be1 = (const float*)d_in[4];
    const float* m1  = (const float*)d_in[5];
    const float* v1  = (const float*)d_in[6];
    const float* w2  = (const float*)d_in[7];
    const float* b2  = (const float*)d_in[8];
    const float* g2  = (const float*)d_in[9];
    const float* be2 = (const float*)d_in[10];
    const float* m2  = (const float*)d_in[11];
    const float* v2  = (const float*)d_in[12];
    const float* w3  = (const float*)d_in[13];
    const float* b3  = (const float*)d_in[14];

    prep_kernel<<<GG, 256>>>(x, w1, b1, g1, be1, m1, v1,
                             w2, b2, g2, be2, m2, v2, w3, b3);
    sample_kernel<<<dim3(NPTS, NSAMP / 128), 128>>>();
    scan_kernel<<<NPTS, 128>>>();
    refine_kernel<<<MAXWORK, 64>>>();
    main_kernel<<<dim3(GG / CELLS, GG), 128>>>();
    finalize_kernel<<<1, 128>>>((float*)d_out);
}